// round 2
// baseline (speedup 1.0000x reference)
#include <cuda_runtime.h>
#include <cuda_bf16.h>

#define NN    32768
#define FIN   32
#define HC    64
#define HEADS 4
#define EE    524288
#define ET    (EE + NN)     // 557056 edges incl. self-loops
#define BATCH 64
#define TT    512
#define OUTD  24

// ---------------- scratch (device globals; no allocation) ----------------
__device__ __align__(16) float g_h1[(size_t)NN * 256];     // GAT1 GEMM out
__device__ __align__(16) float g_h2in[(size_t)NN * 256];   // GAT1 agg + b1 + elu
__device__ __align__(16) float g_t2[(size_t)NN * 64];      // GAT2 GEMM out
__device__ __align__(16) float g_seqin[(size_t)NN * 64];   // GAT2 agg + b2 + elu
__device__ __align__(16) float g_seq1[(size_t)NN * 64];    // GRU layer-0 output seq
__device__ __align__(16) float g_gi[(size_t)NN * 192];     // GRU input gates
__device__ __align__(16) float g_as1[NN * 4];
__device__ __align__(16) float g_ad1[NN * 4];
__device__ float g_as2[NN];
__device__ float g_ad2[NN];
__device__ int   g_deg[NN];
__device__ int   g_rowptr[NN + 1];
__device__ int   g_cursor[NN];
__device__ int   g_csr[ET];
__device__ __align__(16) float g_WT0[64 * 192];            // Wih0^T (k-major)
__device__ __align__(16) float g_WT1[64 * 192];
__device__ __align__(16) float g_hT[BATCH * HC];

// ---------------- helpers ----------------
__device__ __forceinline__ float lrelu(float v)  { return v > 0.f ? v : 0.2f * v; }
__device__ __forceinline__ float elu1(float v)   { return v > 0.f ? v : (__expf(v) - 1.f); }
__device__ __forceinline__ float sigm(float v)   { return 1.f / (1.f + __expf(-v)); }
__device__ __forceinline__ float tanh_f(float v) { return 2.f / (1.f + __expf(-2.f * v)) - 1.f; }

__device__ __forceinline__ float wred(float v) {
#pragma unroll
    for (int o = 16; o; o >>= 1) v += __shfl_xor_sync(0xffffffffu, v, o);
    return v;
}
__device__ __forceinline__ float wmaxr(float v) {
#pragma unroll
    for (int o = 16; o; o >>= 1) v = fmaxf(v, __shfl_xor_sync(0xffffffffu, v, o));
    return v;
}

// ---------------- CSR build ----------------
__global__ void zero_deg_kernel() {
    int i = blockIdx.x * blockDim.x + threadIdx.x;
    if (i < NN) g_deg[i] = 0;
}

__global__ void hist_kernel(const int* __restrict__ ei) {
    int i = blockIdx.x * blockDim.x + threadIdx.x;
    if (i >= ET) return;
    int dst = (i < EE) ? ei[EE + i] : (i - EE);
    atomicAdd(&g_deg[dst], 1);
}

__global__ void scan_kernel() {   // 1 block, 1024 threads, 32 nodes/thread
    __shared__ int wsum[32];
    int tid = threadIdx.x;
    int vals[32];
    int base = tid * 32;
    int s = 0;
#pragma unroll
    for (int j = 0; j < 32; j++) { int v = g_deg[base + j]; vals[j] = v; s += v; }
    int lane = tid & 31, wid = tid >> 5;
    int inc = s;
#pragma unroll
    for (int o = 1; o < 32; o <<= 1) {
        int y = __shfl_up_sync(0xffffffffu, inc, o);
        if (lane >= o) inc += y;
    }
    if (lane == 31) wsum[wid] = inc;
    __syncthreads();
    if (wid == 0) {
        int v = wsum[lane];
#pragma unroll
        for (int o = 1; o < 32; o <<= 1) {
            int y = __shfl_up_sync(0xffffffffu, v, o);
            if (lane >= o) v += y;
        }
        wsum[lane] = v;
    }
    __syncthreads();
    int off = inc - s + (wid > 0 ? wsum[wid - 1] : 0);
#pragma unroll
    for (int j = 0; j < 32; j++) {
        g_rowptr[base + j] = off;
        g_cursor[base + j] = off;
        off += vals[j];
    }
    if (tid == 1023) g_rowptr[NN] = off;
}

__global__ void scatter_kernel(const int* __restrict__ ei) {
    int i = blockIdx.x * blockDim.x + threadIdx.x;
    if (i >= ET) return;
    int src, dst;
    if (i < EE) { src = ei[i]; dst = ei[EE + i]; }
    else        { src = dst = i - EE; }
    int pos = atomicAdd(&g_cursor[dst], 1);
    g_csr[pos] = src;
}

// ---------------- GAT layer 1: GEMM + attention coefficients ----------------
__device__ __forceinline__ void gat1_store_alpha(int node, const float acc[8],
                                                 const float* aS, const float* aD, int lane) {
#pragma unroll
    for (int j = 0; j < 8; j++) g_h1[(size_t)node * 256 + lane + 32 * j] = acc[j];
    float p0 = acc[0] * aS[lane]       + acc[1] * aS[lane + 32];
    float p1 = acc[2] * aS[64 + lane]  + acc[3] * aS[96 + lane];
    float p2 = acc[4] * aS[128 + lane] + acc[5] * aS[160 + lane];
    float p3 = acc[6] * aS[192 + lane] + acc[7] * aS[224 + lane];
    float q0 = acc[0] * aD[lane]       + acc[1] * aD[lane + 32];
    float q1 = acc[2] * aD[64 + lane]  + acc[3] * aD[96 + lane];
    float q2 = acc[4] * aD[128 + lane] + acc[5] * aD[160 + lane];
    float q3 = acc[6] * aD[192 + lane] + acc[7] * aD[224 + lane];
    p0 = wred(p0); p1 = wred(p1); p2 = wred(p2); p3 = wred(p3);
    q0 = wred(q0); q1 = wred(q1); q2 = wred(q2); q3 = wred(q3);
    if (lane == 0) {
        *(float4*)&g_as1[(size_t)node * 4] = make_float4(p0, p1, p2, p3);
        *(float4*)&g_ad1[(size_t)node * 4] = make_float4(q0, q1, q2, q3);
    }
}

__global__ __launch_bounds__(256) void gat1_gemm_kernel(
        const float* __restrict__ x, const float* __restrict__ W1,
        const float* __restrict__ a_src, const float* __restrict__ a_dst) {
    __shared__ float W1s[FIN * 256];   // 32 KB, k-major (same layout as W1)
    __shared__ float xs[16 * FIN];
    __shared__ float aS[256], aD[256];
    int tid = threadIdx.x, lane = tid & 31, w = tid >> 5;
#pragma unroll
    for (int i = 0; i < 8; i++)
        ((float4*)W1s)[tid + 256 * i] = ((const float4*)W1)[tid + 256 * i];
    aS[tid] = a_src[tid];
    aD[tid] = a_dst[tid];
    int nodeBase = blockIdx.x * 16 + w * 2;
    xs[(w * 2) * FIN + lane]     = x[(size_t)nodeBase * FIN + lane];
    xs[(w * 2 + 1) * FIN + lane] = x[(size_t)(nodeBase + 1) * FIN + lane];
    __syncthreads();
    float acc0[8] = {0,0,0,0,0,0,0,0};
    float acc1[8] = {0,0,0,0,0,0,0,0};
#pragma unroll 4
    for (int k = 0; k < FIN; k++) {
        float x0 = xs[(w * 2) * FIN + k];
        float x1 = xs[(w * 2 + 1) * FIN + k];
#pragma unroll
        for (int j = 0; j < 8; j++) {
            float wv = W1s[k * 256 + lane + 32 * j];
            acc0[j] = fmaf(x0, wv, acc0[j]);
            acc1[j] = fmaf(x1, wv, acc1[j]);
        }
    }
    gat1_store_alpha(nodeBase,     acc0, aS, aD, lane);
    gat1_store_alpha(nodeBase + 1, acc1, aS, aD, lane);
}

// ---------------- GAT layer 1 aggregation (fused edge softmax) ----------------
__global__ __launch_bounds__(256) void gat1_agg_kernel(const float* __restrict__ b1) {
    int node = blockIdx.x * 8 + (threadIdx.x >> 5);
    int lane = threadIdx.x & 31;
    int beg = g_rowptr[node], end = g_rowptr[node + 1];
    float4 ad = *(const float4*)&g_ad1[(size_t)node * 4];
    float m0 = -1e30f, m1 = -1e30f, m2 = -1e30f, m3 = -1e30f;
    for (int e = beg + lane; e < end; e += 32) {
        int s = __ldg(&g_csr[e]);
        float4 as = *(const float4*)&g_as1[(size_t)s * 4];
        m0 = fmaxf(m0, lrelu(as.x + ad.x));
        m1 = fmaxf(m1, lrelu(as.y + ad.y));
        m2 = fmaxf(m2, lrelu(as.z + ad.z));
        m3 = fmaxf(m3, lrelu(as.w + ad.w));
    }
    m0 = wmaxr(m0); m1 = wmaxr(m1); m2 = wmaxr(m2); m3 = wmaxr(m3);
    float s0 = 0.f, s1 = 0.f, s2 = 0.f, s3 = 0.f;
    for (int e = beg + lane; e < end; e += 32) {
        int s = __ldg(&g_csr[e]);
        float4 as = *(const float4*)&g_as1[(size_t)s * 4];
        s0 += __expf(lrelu(as.x + ad.x) - m0);
        s1 += __expf(lrelu(as.y + ad.y) - m1);
        s2 += __expf(lrelu(as.z + ad.z) - m2);
        s3 += __expf(lrelu(as.w + ad.w) - m3);
    }
    s0 = wred(s0); s1 = wred(s1); s2 = wred(s2); s3 = wred(s3);
    float i0 = 1.f / (s0 + 1e-16f), i1 = 1.f / (s1 + 1e-16f);
    float i2 = 1.f / (s2 + 1e-16f), i3 = 1.f / (s3 + 1e-16f);
    float acc[8] = {0,0,0,0,0,0,0,0};
    for (int e = beg; e < end; ++e) {
        int s = __ldg(&g_csr[e]);
        float4 as = *(const float4*)&g_as1[(size_t)s * 4];
        float w0 = __expf(lrelu(as.x + ad.x) - m0) * i0;
        float w1 = __expf(lrelu(as.y + ad.y) - m1) * i1;
        float w2 = __expf(lrelu(as.z + ad.z) - m2) * i2;
        float w3 = __expf(lrelu(as.w + ad.w) - m3) * i3;
        const float* hr = g_h1 + (size_t)s * 256;
        acc[0] = fmaf(hr[lane],       w0, acc[0]);
        acc[1] = fmaf(hr[lane +  32], w0, acc[1]);
        acc[2] = fmaf(hr[lane +  64], w1, acc[2]);
        acc[3] = fmaf(hr[lane +  96], w1, acc[3]);
        acc[4] = fmaf(hr[lane + 128], w2, acc[4]);
        acc[5] = fmaf(hr[lane + 160], w2, acc[5]);
        acc[6] = fmaf(hr[lane + 192], w3, acc[6]);
        acc[7] = fmaf(hr[lane + 224], w3, acc[7]);
    }
#pragma unroll
    for (int j = 0; j < 8; j++) {
        int col = lane + 32 * j;
        g_h2in[(size_t)node * 256 + col] = elu1(acc[j] + __ldg(&b1[col]));
    }
}

// ---------------- GAT layer 2: GEMM + attention coefficients ----------------
// dyn smem: W2s[256*64] + rb[8 warps][2][256] + aS[64] + aD[64]
__global__ __launch_bounds__(256) void gat2_gemm_kernel(
        const float* __restrict__ W2, const float* __restrict__ a_src,
        const float* __restrict__ a_dst) {
    extern __shared__ float sm[];
    float* W2s = sm;               // 16384
    float* rb  = sm + 16384;       // 4096
    float* aS  = sm + 16384 + 4096;
    float* aD  = aS + 64;
    int tid = threadIdx.x, lane = tid & 31, w = tid >> 5;
    for (int i = tid; i < 4096; i += 256)
        ((float4*)W2s)[i] = ((const float4*)W2)[i];
    if (tid < 64) { aS[tid] = a_src[tid]; aD[tid] = a_dst[tid]; }
    __syncthreads();
    float* rb0 = rb + w * 512;
    float* rb1 = rb0 + 256;
#pragma unroll 1
    for (int iter = 0; iter < 4; iter++) {
        int n0 = blockIdx.x * 64 + w * 8 + iter * 2;
        int n1 = n0 + 1;
#pragma unroll
        for (int i = 0; i < 8; i++) {
            rb0[lane + 32 * i] = g_h2in[(size_t)n0 * 256 + lane + 32 * i];
            rb1[lane + 32 * i] = g_h2in[(size_t)n1 * 256 + lane + 32 * i];
        }
        __syncwarp();
        float a00 = 0.f, a01 = 0.f, a10 = 0.f, a11 = 0.f;
#pragma unroll 8
        for (int k = 0; k < 256; k++) {
            float wv0 = W2s[k * 64 + lane];
            float wv1 = W2s[k * 64 + lane + 32];
            float r0 = rb0[k], r1 = rb1[k];
            a00 = fmaf(r0, wv0, a00);
            a01 = fmaf(r0, wv1, a01);
            a10 = fmaf(r1, wv0, a10);
            a11 = fmaf(r1, wv1, a11);
        }
        g_t2[(size_t)n0 * 64 + lane]      = a00;
        g_t2[(size_t)n0 * 64 + lane + 32] = a01;
        g_t2[(size_t)n1 * 64 + lane]      = a10;
        g_t2[(size_t)n1 * 64 + lane + 32] = a11;
        float p0 = wred(a00 * aS[lane] + a01 * aS[lane + 32]);
        float q0 = wred(a00 * aD[lane] + a01 * aD[lane + 32]);
        float p1 = wred(a10 * aS[lane] + a11 * aS[lane + 32]);
        float q1 = wred(a10 * aD[lane] + a11 * aD[lane + 32]);
        if (lane == 0) {
            g_as2[n0] = p0; g_ad2[n0] = q0;
            g_as2[n1] = p1; g_ad2[n1] = q1;
        }
        __syncwarp();
    }
}

// ---------------- GAT layer 2 aggregation ----------------
__global__ __launch_bounds__(256) void gat2_agg_kernel(const float* __restrict__ b2) {
    int node = blockIdx.x * 8 + (threadIdx.x >> 5);
    int lane = threadIdx.x & 31;
    int beg = g_rowptr[node], end = g_rowptr[node + 1];
    float ad = g_ad2[node];
    float m = -1e30f;
    for (int e = beg + lane; e < end; e += 32)
        m = fmaxf(m, lrelu(__ldg(&g_as2[__ldg(&g_csr[e])]) + ad));
    m = wmaxr(m);
    float su = 0.f;
    for (int e = beg + lane; e < end; e += 32)
        su += __expf(lrelu(__ldg(&g_as2[__ldg(&g_csr[e])]) + ad) - m);
    su = wred(su);
    float inv = 1.f / (su + 1e-16f);
    float acc0 = 0.f, acc1 = 0.f;
    for (int e = beg; e < end; ++e) {
        int s = __ldg(&g_csr[e]);
        float wgt = __expf(lrelu(__ldg(&g_as2[s]) + ad) - m) * inv;
        const float* tr = g_t2 + (size_t)s * 64;
        acc0 = fmaf(tr[lane],      wgt, acc0);
        acc1 = fmaf(tr[lane + 32], wgt, acc1);
    }
    g_seqin[(size_t)node * 64 + lane]      = elu1(acc0 + __ldg(&b2[lane]));
    g_seqin[(size_t)node * 64 + lane + 32] = elu1(acc1 + __ldg(&b2[lane + 32]));
}

// ---------------- GRU weight transpose ----------------
__global__ void transpose_wih_kernel(const float* __restrict__ Wih0,
                                     const float* __restrict__ Wih1) {
    int i = blockIdx.x * blockDim.x + threadIdx.x;
    if (i >= 192 * 64) return;
    int j = i / 64, k = i % 64;
    g_WT0[k * 192 + j] = Wih0[i];
    g_WT1[k * 192 + j] = Wih1[i];
}

// ---------------- GRU input-gate GEMM: gi = X @ Wih^T + bih ----------------
// dyn smem: WT[64*192] + rows[8*64]
__global__ __launch_bounds__(192) void gru_in_gemm_kernel(int layer,
                                                          const float* __restrict__ bih) {
    extern __shared__ float sm[];
    float* WTs  = sm;          // 12288
    float* rows = sm + 12288;  // 512
    const float* X  = layer ? g_seq1 : g_seqin;
    const float* WT = layer ? g_WT1  : g_WT0;
    int j = threadIdx.x;
    for (int i = j; i < 12288; i += 192) WTs[i] = WT[i];
    float b = bih[j];
    __syncthreads();
#pragma unroll 1
    for (int gidx = 0; gidx < 8; gidx++) {
        int base = blockIdx.x * 64 + gidx * 8;
        for (int i = j; i < 512; i += 192) rows[i] = X[(size_t)base * 64 + i];
        __syncthreads();
        float acc[8];
#pragma unroll
        for (int n = 0; n < 8; n++) acc[n] = b;
#pragma unroll 8
        for (int k = 0; k < 64; k++) {
            float wv = WTs[k * 192 + j];
#pragma unroll
            for (int n = 0; n < 8; n++)
                acc[n] = fmaf(rows[n * 64 + k], wv, acc[n]);
        }
#pragma unroll
        for (int n = 0; n < 8; n++)
            g_gi[(size_t)(base + n) * 192 + j] = acc[n];
        __syncthreads();
    }
}

// ---------------- GRU recurrence ----------------
__global__ __launch_bounds__(192, 1) void gru_rec_kernel(
        const float* __restrict__ Whh, const float* __restrict__ bhh, int store_seq) {
    int graph = blockIdx.x;
    int j = threadIdx.x;
    float w[64];
#pragma unroll
    for (int k4 = 0; k4 < 16; k4++) {
        float4 v = ((const float4*)Whh)[j * 16 + k4];
        w[k4 * 4] = v.x; w[k4 * 4 + 1] = v.y; w[k4 * 4 + 2] = v.z; w[k4 * 4 + 3] = v.w;
    }
    float bh = bhh[j];
    __shared__ float h[64];
    __shared__ float gh[192];
    if (j < 64) h[j] = 0.f;
    __syncthreads();
    const float* gi = g_gi + (size_t)graph * 512 * 192;
    float* seq = g_seq1 + (size_t)graph * 512 * 64;
    for (int t = 0; t < 512; t++) {
        float a0 = 0.f, a1 = 0.f, a2 = 0.f, a3 = 0.f;
#pragma unroll
        for (int k = 0; k < 64; k += 4) {
            a0 = fmaf(w[k],     h[k],     a0);
            a1 = fmaf(w[k + 1], h[k + 1], a1);
            a2 = fmaf(w[k + 2], h[k + 2], a2);
            a3 = fmaf(w[k + 3], h[k + 3], a3);
        }
        gh[j] = (a0 + a1) + (a2 + a3) + bh;
        __syncthreads();
        if (j < 64) {
            const float* g = gi + (size_t)t * 192;
            float r = sigm(g[j] + gh[j]);
            float z = sigm(g[64 + j] + gh[64 + j]);
            float n = tanh_f(g[128 + j] + r * gh[128 + j]);
            float hn = (1.f - z) * n + z * h[j];
            h[j] = hn;
            if (store_seq) seq[(size_t)t * 64 + j] = hn;
        }
        __syncthreads();
    }
    if (!store_seq && j < 64) g_hT[graph * 64 + j] = h[j];
}

// ---------------- Linear head ----------------
__global__ void head_kernel(const float* __restrict__ Wl, const float* __restrict__ bl,
                            float* __restrict__ out) {
    int b = blockIdx.x, lane = threadIdx.x;
    if (lane >= OUTD) return;
    float acc = bl[lane];
    const float* hr = g_hT + b * 64;
    const float* wr = Wl + lane * 64;
#pragma unroll 8
    for (int k = 0; k < 64; k++) acc = fmaf(hr[k], wr[k], acc);
    out[b * OUTD + lane] = acc;
}

// ---------------- launch ----------------
extern "C" void kernel_launch(void* const* d_in, const int* in_sizes, int n_in,
                              void* d_out, int out_size) {
    const float* x      = (const float*)d_in[0];
    const int*   ei     = (const int*)d_in[1];
    const float* W1     = (const float*)d_in[3];
    const float* a_src1 = (const float*)d_in[4];
    const float* a_dst1 = (const float*)d_in[5];
    const float* b1     = (const float*)d_in[6];
    const float* W2     = (const float*)d_in[7];
    const float* a_src2 = (const float*)d_in[8];
    const float* a_dst2 = (const float*)d_in[9];
    const float* b2     = (const float*)d_in[10];
    const float* Wih0   = (const float*)d_in[11];
    const float* Whh0   = (const float*)d_in[12];
    const float* bih0   = (const float*)d_in[13];
    const float* bhh0   = (const float*)d_in[14];
    const float* Wih1   = (const float*)d_in[15];
    const float* Whh1   = (const float*)d_in[16];
    const float* bih1   = (const float*)d_in[17];
    const float* bhh1   = (const float*)d_in[18];
    const float* Wl     = (const float*)d_in[19];
    const float* bl     = (const float*)d_in[20];
    float* out = (float*)d_out;

    cudaFuncSetAttribute(gat2_gemm_kernel,
                         cudaFuncAttributeMaxDynamicSharedMemorySize, 82432);
    cudaFuncSetAttribute(gru_in_gemm_kernel,
                         cudaFuncAttributeMaxDynamicSharedMemorySize, 51200);

    zero_deg_kernel<<<128, 256>>>();
    hist_kernel<<<2176, 256>>>(ei);
    scan_kernel<<<1, 1024>>>();
    scatter_kernel<<<2176, 256>>>(ei);

    gat1_gemm_kernel<<<2048, 256>>>(x, W1, a_src1, a_dst1);
    gat1_agg_kernel<<<4096, 256>>>(b1);

    gat2_gemm_kernel<<<512, 256, 82432>>>(W2, a_src2, a_dst2);
    gat2_agg_kernel<<<4096, 256>>>(b2);

    transpose_wih_kernel<<<48, 256>>>(Wih0, Wih1);

    gru_in_gemm_kernel<<<512, 192, 51200>>>(0, bih0);
    gru_rec_kernel<<<64, 192>>>(Whh0, bhh0, 1);

    gru_in_gemm_kernel<<<512, 192, 51200>>>(1, bih1);
    gru_rec_kernel<<<64, 192>>>(Whh1, bhh1, 0);

    head_kernel<<<64, 32>>>(Wl, bl, out);
}

// round 3
// speedup vs baseline: 2.2753x; 2.2753x over previous
#include <cuda_runtime.h>
#include <cuda_bf16.h>

#define NN    32768
#define FIN   32
#define HC    64
#define HEADS 4
#define EE    524288
#define ET    (EE + NN)     // 557056 edges incl. self-loops
#define BATCH 64
#define TT    512
#define OUTD  24

// ---------------- scratch (device globals; no allocation) ----------------
__device__ __align__(16) float g_h1[(size_t)NN * 256];     // GAT1 GEMM out
__device__ __align__(16) float g_h2in[(size_t)NN * 256];   // GAT1 agg + b1 + elu
__device__ __align__(16) float g_t2[(size_t)NN * 64];      // GAT2 GEMM out
__device__ __align__(16) float g_seqin[(size_t)NN * 64];   // GAT2 agg + b2 + elu
__device__ __align__(16) float g_gi[(size_t)NN * 192];     // GRU L0 input gates
__device__ __align__(16) float g_as1[NN * 4];
__device__ __align__(16) float g_ad1[NN * 4];
__device__ float g_as2[NN];
__device__ float g_ad2[NN];
__device__ int   g_deg[NN];
__device__ int   g_rowptr[NN + 1];
__device__ int   g_cursor[NN];
__device__ int   g_csr[ET];
__device__ __align__(16) float g_WT0[64 * 192];            // Wih0^T (k-major)

// ---------------- helpers ----------------
__device__ __forceinline__ float lrelu(float v)  { return v > 0.f ? v : 0.2f * v; }
__device__ __forceinline__ float elu1(float v)   { return v > 0.f ? v : (__expf(v) - 1.f); }
__device__ __forceinline__ float sigm(float v)   { return 1.f / (1.f + __expf(-v)); }
__device__ __forceinline__ float tanh_f(float v) { return 2.f / (1.f + __expf(-2.f * v)) - 1.f; }

__device__ __forceinline__ float wred(float v) {
#pragma unroll
    for (int o = 16; o; o >>= 1) v += __shfl_xor_sync(0xffffffffu, v, o);
    return v;
}
__device__ __forceinline__ float wmaxr(float v) {
#pragma unroll
    for (int o = 16; o; o >>= 1) v = fmaxf(v, __shfl_xor_sync(0xffffffffu, v, o));
    return v;
}

// packed fp32x2 FMA (sm_103a FFMA2)
__device__ __forceinline__ void fma2(unsigned long long& acc,
                                     unsigned long long a, unsigned long long b) {
    asm("fma.rn.f32x2 %0, %1, %2, %0;" : "+l"(acc) : "l"(a), "l"(b));
}
__device__ __forceinline__ float unpack_sum(unsigned long long v) {
    unsigned lo = (unsigned)v, hi = (unsigned)(v >> 32);
    return __uint_as_float(lo) + __uint_as_float(hi);
}

// ---------------- CSR build ----------------
__global__ void zero_deg_kernel() {
    int i = blockIdx.x * blockDim.x + threadIdx.x;
    if (i < NN) g_deg[i] = 0;
}

__global__ void hist_kernel(const int* __restrict__ ei) {
    int i = blockIdx.x * blockDim.x + threadIdx.x;
    if (i >= ET) return;
    int dst = (i < EE) ? ei[EE + i] : (i - EE);
    atomicAdd(&g_deg[dst], 1);
}

__global__ void scan_kernel() {   // 1 block, 1024 threads, 32 nodes/thread
    __shared__ int wsum[32];
    int tid = threadIdx.x;
    int vals[32];
    int base = tid * 32;
    int s = 0;
#pragma unroll
    for (int j = 0; j < 32; j++) { int v = g_deg[base + j]; vals[j] = v; s += v; }
    int lane = tid & 31, wid = tid >> 5;
    int inc = s;
#pragma unroll
    for (int o = 1; o < 32; o <<= 1) {
        int y = __shfl_up_sync(0xffffffffu, inc, o);
        if (lane >= o) inc += y;
    }
    if (lane == 31) wsum[wid] = inc;
    __syncthreads();
    if (wid == 0) {
        int v = wsum[lane];
#pragma unroll
        for (int o = 1; o < 32; o <<= 1) {
            int y = __shfl_up_sync(0xffffffffu, v, o);
            if (lane >= o) v += y;
        }
        wsum[lane] = v;
    }
    __syncthreads();
    int off = inc - s + (wid > 0 ? wsum[wid - 1] : 0);
#pragma unroll
    for (int j = 0; j < 32; j++) {
        g_rowptr[base + j] = off;
        g_cursor[base + j] = off;
        off += vals[j];
    }
    if (tid == 1023) g_rowptr[NN] = off;
}

__global__ void scatter_kernel(const int* __restrict__ ei) {
    int i = blockIdx.x * blockDim.x + threadIdx.x;
    if (i >= ET) return;
    int src, dst;
    if (i < EE) { src = ei[i]; dst = ei[EE + i]; }
    else        { src = dst = i - EE; }
    int pos = atomicAdd(&g_cursor[dst], 1);
    g_csr[pos] = src;
}

// ---------------- GAT layer 1: GEMM + attention coefficients ----------------
__device__ __forceinline__ void gat1_store_alpha(int node, const float acc[8],
                                                 const float* aS, const float* aD, int lane) {
#pragma unroll
    for (int j = 0; j < 8; j++) g_h1[(size_t)node * 256 + lane + 32 * j] = acc[j];
    float p0 = acc[0] * aS[lane]       + acc[1] * aS[lane + 32];
    float p1 = acc[2] * aS[64 + lane]  + acc[3] * aS[96 + lane];
    float p2 = acc[4] * aS[128 + lane] + acc[5] * aS[160 + lane];
    float p3 = acc[6] * aS[192 + lane] + acc[7] * aS[224 + lane];
    float q0 = acc[0] * aD[lane]       + acc[1] * aD[lane + 32];
    float q1 = acc[2] * aD[64 + lane]  + acc[3] * aD[96 + lane];
    float q2 = acc[4] * aD[128 + lane] + acc[5] * aD[160 + lane];
    float q3 = acc[6] * aD[192 + lane] + acc[7] * aD[224 + lane];
    p0 = wred(p0); p1 = wred(p1); p2 = wred(p2); p3 = wred(p3);
    q0 = wred(q0); q1 = wred(q1); q2 = wred(q2); q3 = wred(q3);
    if (lane == 0) {
        *(float4*)&g_as1[(size_t)node * 4] = make_float4(p0, p1, p2, p3);
        *(float4*)&g_ad1[(size_t)node * 4] = make_float4(q0, q1, q2, q3);
    }
}

__global__ __launch_bounds__(256) void gat1_gemm_kernel(
        const float* __restrict__ x, const float* __restrict__ W1,
        const float* __restrict__ a_src, const float* __restrict__ a_dst) {
    __shared__ float W1s[FIN * 256];   // 32 KB, k-major (same layout as W1)
    __shared__ float xs[16 * FIN];
    __shared__ float aS[256], aD[256];
    int tid = threadIdx.x, lane = tid & 31, w = tid >> 5;
#pragma unroll
    for (int i = 0; i < 8; i++)
        ((float4*)W1s)[tid + 256 * i] = ((const float4*)W1)[tid + 256 * i];
    aS[tid] = a_src[tid];
    aD[tid] = a_dst[tid];
    int nodeBase = blockIdx.x * 16 + w * 2;
    xs[(w * 2) * FIN + lane]     = x[(size_t)nodeBase * FIN + lane];
    xs[(w * 2 + 1) * FIN + lane] = x[(size_t)(nodeBase + 1) * FIN + lane];
    __syncthreads();
    float acc0[8] = {0,0,0,0,0,0,0,0};
    float acc1[8] = {0,0,0,0,0,0,0,0};
#pragma unroll 4
    for (int k = 0; k < FIN; k++) {
        float x0 = xs[(w * 2) * FIN + k];
        float x1 = xs[(w * 2 + 1) * FIN + k];
#pragma unroll
        for (int j = 0; j < 8; j++) {
            float wv = W1s[k * 256 + lane + 32 * j];
            acc0[j] = fmaf(x0, wv, acc0[j]);
            acc1[j] = fmaf(x1, wv, acc1[j]);
        }
    }
    gat1_store_alpha(nodeBase,     acc0, aS, aD, lane);
    gat1_store_alpha(nodeBase + 1, acc1, aS, aD, lane);
}

// ---------------- GAT layer 1 aggregation (fused edge softmax) ----------------
__global__ __launch_bounds__(256) void gat1_agg_kernel(const float* __restrict__ b1) {
    int node = blockIdx.x * 8 + (threadIdx.x >> 5);
    int lane = threadIdx.x & 31;
    int beg = g_rowptr[node], end = g_rowptr[node + 1];
    float4 ad = *(const float4*)&g_ad1[(size_t)node * 4];
    float m0 = -1e30f, m1 = -1e30f, m2 = -1e30f, m3 = -1e30f;
    for (int e = beg + lane; e < end; e += 32) {
        int s = __ldg(&g_csr[e]);
        float4 as = *(const float4*)&g_as1[(size_t)s * 4];
        m0 = fmaxf(m0, lrelu(as.x + ad.x));
        m1 = fmaxf(m1, lrelu(as.y + ad.y));
        m2 = fmaxf(m2, lrelu(as.z + ad.z));
        m3 = fmaxf(m3, lrelu(as.w + ad.w));
    }
    m0 = wmaxr(m0); m1 = wmaxr(m1); m2 = wmaxr(m2); m3 = wmaxr(m3);
    float s0 = 0.f, s1 = 0.f, s2 = 0.f, s3 = 0.f;
    for (int e = beg + lane; e < end; e += 32) {
        int s = __ldg(&g_csr[e]);
        float4 as = *(const float4*)&g_as1[(size_t)s * 4];
        s0 += __expf(lrelu(as.x + ad.x) - m0);
        s1 += __expf(lrelu(as.y + ad.y) - m1);
        s2 += __expf(lrelu(as.z + ad.z) - m2);
        s3 += __expf(lrelu(as.w + ad.w) - m3);
    }
    s0 = wred(s0); s1 = wred(s1); s2 = wred(s2); s3 = wred(s3);
    float i0 = 1.f / (s0 + 1e-16f), i1 = 1.f / (s1 + 1e-16f);
    float i2 = 1.f / (s2 + 1e-16f), i3 = 1.f / (s3 + 1e-16f);
    float acc[8] = {0,0,0,0,0,0,0,0};
    for (int e = beg; e < end; ++e) {
        int s = __ldg(&g_csr[e]);
        float4 as = *(const float4*)&g_as1[(size_t)s * 4];
        float w0 = __expf(lrelu(as.x + ad.x) - m0) * i0;
        float w1 = __expf(lrelu(as.y + ad.y) - m1) * i1;
        float w2 = __expf(lrelu(as.z + ad.z) - m2) * i2;
        float w3 = __expf(lrelu(as.w + ad.w) - m3) * i3;
        const float* hr = g_h1 + (size_t)s * 256;
        acc[0] = fmaf(hr[lane],       w0, acc[0]);
        acc[1] = fmaf(hr[lane +  32], w0, acc[1]);
        acc[2] = fmaf(hr[lane +  64], w1, acc[2]);
        acc[3] = fmaf(hr[lane +  96], w1, acc[3]);
        acc[4] = fmaf(hr[lane + 128], w2, acc[4]);
        acc[5] = fmaf(hr[lane + 160], w2, acc[5]);
        acc[6] = fmaf(hr[lane + 192], w3, acc[6]);
        acc[7] = fmaf(hr[lane + 224], w3, acc[7]);
    }
#pragma unroll
    for (int j = 0; j < 8; j++) {
        int col = lane + 32 * j;
        g_h2in[(size_t)node * 256 + col] = elu1(acc[j] + __ldg(&b1[col]));
    }
}

// ---------------- GAT layer 2: GEMM + attention coefficients ----------------
__global__ __launch_bounds__(256) void gat2_gemm_kernel(
        const float* __restrict__ W2, const float* __restrict__ a_src,
        const float* __restrict__ a_dst) {
    extern __shared__ float sm[];
    float* W2s = sm;               // 16384
    float* rb  = sm + 16384;       // 4096
    float* aS  = sm + 16384 + 4096;
    float* aD  = aS + 64;
    int tid = threadIdx.x, lane = tid & 31, w = tid >> 5;
    for (int i = tid; i < 4096; i += 256)
        ((float4*)W2s)[i] = ((const float4*)W2)[i];
    if (tid < 64) { aS[tid] = a_src[tid]; aD[tid] = a_dst[tid]; }
    __syncthreads();
    float* rb0 = rb + w * 512;
    float* rb1 = rb0 + 256;
#pragma unroll 1
    for (int iter = 0; iter < 4; iter++) {
        int n0 = blockIdx.x * 64 + w * 8 + iter * 2;
        int n1 = n0 + 1;
#pragma unroll
        for (int i = 0; i < 8; i++) {
            rb0[lane + 32 * i] = g_h2in[(size_t)n0 * 256 + lane + 32 * i];
            rb1[lane + 32 * i] = g_h2in[(size_t)n1 * 256 + lane + 32 * i];
        }
        __syncwarp();
        float a00 = 0.f, a01 = 0.f, a10 = 0.f, a11 = 0.f;
#pragma unroll 8
        for (int k = 0; k < 256; k++) {
            float wv0 = W2s[k * 64 + lane];
            float wv1 = W2s[k * 64 + lane + 32];
            float r0 = rb0[k], r1 = rb1[k];
            a00 = fmaf(r0, wv0, a00);
            a01 = fmaf(r0, wv1, a01);
            a10 = fmaf(r1, wv0, a10);
            a11 = fmaf(r1, wv1, a11);
        }
        g_t2[(size_t)n0 * 64 + lane]      = a00;
        g_t2[(size_t)n0 * 64 + lane + 32] = a01;
        g_t2[(size_t)n1 * 64 + lane]      = a10;
        g_t2[(size_t)n1 * 64 + lane + 32] = a11;
        float p0 = wred(a00 * aS[lane] + a01 * aS[lane + 32]);
        float q0 = wred(a00 * aD[lane] + a01 * aD[lane + 32]);
        float p1 = wred(a10 * aS[lane] + a11 * aS[lane + 32]);
        float q1 = wred(a10 * aD[lane] + a11 * aD[lane + 32]);
        if (lane == 0) {
            g_as2[n0] = p0; g_ad2[n0] = q0;
            g_as2[n1] = p1; g_ad2[n1] = q1;
        }
        __syncwarp();
    }
}

// ---------------- GAT layer 2 aggregation ----------------
__global__ __launch_bounds__(256) void gat2_agg_kernel(const float* __restrict__ b2) {
    int node = blockIdx.x * 8 + (threadIdx.x >> 5);
    int lane = threadIdx.x & 31;
    int beg = g_rowptr[node], end = g_rowptr[node + 1];
    float ad = g_ad2[node];
    float m = -1e30f;
    for (int e = beg + lane; e < end; e += 32)
        m = fmaxf(m, lrelu(__ldg(&g_as2[__ldg(&g_csr[e])]) + ad));
    m = wmaxr(m);
    float su = 0.f;
    for (int e = beg + lane; e < end; e += 32)
        su += __expf(lrelu(__ldg(&g_as2[__ldg(&g_csr[e])]) + ad) - m);
    su = wred(su);
    float inv = 1.f / (su + 1e-16f);
    float acc0 = 0.f, acc1 = 0.f;
    for (int e = beg; e < end; ++e) {
        int s = __ldg(&g_csr[e]);
        float wgt = __expf(lrelu(__ldg(&g_as2[s]) + ad) - m) * inv;
        const float* tr = g_t2 + (size_t)s * 64;
        acc0 = fmaf(tr[lane],      wgt, acc0);
        acc1 = fmaf(tr[lane + 32], wgt, acc1);
    }
    g_seqin[(size_t)node * 64 + lane]      = elu1(acc0 + __ldg(&b2[lane]));
    g_seqin[(size_t)node * 64 + lane + 32] = elu1(acc1 + __ldg(&b2[lane + 32]));
}

// ---------------- GRU weight transpose (layer-0 Wih only) ----------------
__global__ void transpose_wih_kernel(const float* __restrict__ Wih0) {
    int i = blockIdx.x * blockDim.x + threadIdx.x;
    if (i >= 192 * 64) return;
    int j = i / 64, k = i % 64;
    g_WT0[k * 192 + j] = Wih0[i];
}

// ---------------- GRU L0 input-gate GEMM: gi = X @ Wih0^T + bih0 ----------------
__global__ __launch_bounds__(192) void gru_in_gemm_kernel(const float* __restrict__ bih) {
    extern __shared__ float sm[];
    float* WTs  = sm;          // 12288
    float* rows = sm + 12288;  // 512
    int j = threadIdx.x;
    for (int i = j; i < 12288; i += 192) WTs[i] = g_WT0[i];
    float b = bih[j];
    __syncthreads();
#pragma unroll 1
    for (int gidx = 0; gidx < 8; gidx++) {
        int base = blockIdx.x * 64 + gidx * 8;
        for (int i = j; i < 512; i += 192) rows[i] = g_seqin[(size_t)base * 64 + i];
        __syncthreads();
        float acc[8];
#pragma unroll
        for (int n = 0; n < 8; n++) acc[n] = b;
#pragma unroll 8
        for (int k = 0; k < 64; k++) {
            float wv = WTs[k * 192 + j];
#pragma unroll
            for (int n = 0; n < 8; n++)
                acc[n] = fmaf(rows[n * 64 + k], wv, acc[n]);
        }
#pragma unroll
        for (int n = 0; n < 8; n++)
            g_gi[(size_t)(base + n) * 192 + j] = acc[n];
        __syncthreads();
    }
}

// ---------------- Fused 2-layer GRU recurrence + head ----------------
// 576 threads: tid 0..191   -> gh0 row (Whh0)
//              tid 192..383 -> gi1 row (Wih1)
//              tid 384..575 -> gh1 row (Whh1)
// Layer-1 runs one step behind layer-0 (software pipeline).
__global__ __launch_bounds__(576, 1) void gru_fused_kernel(
        const float* __restrict__ Whh0, const float* __restrict__ bhh0,
        const float* __restrict__ Wih1, const float* __restrict__ bih1,
        const float* __restrict__ Whh1, const float* __restrict__ bhh1,
        const float* __restrict__ Wl,   const float* __restrict__ bl,
        float* __restrict__ out) {
    __shared__ __align__(16) float S[576];     // [gh0 | gi1 | gh1]
    __shared__ __align__(16) float gi0s[192];
    __shared__ __align__(16) float h0s[64];
    __shared__ __align__(16) float h1s[64];

    int tid = threadIdx.x;
    int graph = blockIdx.x;

    // pick this thread's weight row + dot source + bias
    const float* wrow;
    const float* hsrc;
    float bias;
    if (tid < 192)      { wrow = Whh0 + tid * 64;         hsrc = h0s; bias = bhh0[tid]; }
    else if (tid < 384) { wrow = Wih1 + (tid - 192) * 64; hsrc = h0s; bias = bih1[tid - 192]; }
    else                { wrow = Whh1 + (tid - 384) * 64; hsrc = h1s; bias = bhh1[tid - 384]; }

    unsigned long long w[32];
    const unsigned long long* wp = (const unsigned long long*)wrow;
#pragma unroll
    for (int i = 0; i < 32; i++) w[i] = wp[i];

    if (tid < 64) { h0s[tid] = 0.f; h1s[tid] = 0.f; }

    const float* gi = g_gi + (size_t)graph * 512 * 192;
    float gi_cur = 0.f;
    if (tid < 192) gi_cur = gi[tid];          // gi0[0][j]
    __syncthreads();

    const unsigned long long* hv = (const unsigned long long*)hsrc;

    for (int t = 0; t <= 512; t++) {
        // stage this step's gi0 + prefetch next
        float gi_next = 0.f;
        if (tid < 192) {
            gi0s[tid] = gi_cur;
            int tn = (t + 1 < 512) ? (t + 1) : 511;
            gi_next = gi[(size_t)tn * 192 + tid];
        }
        // uniform GEMV row: 32 packed FFMA2
        unsigned long long a0 = 0, a1 = 0, a2 = 0, a3 = 0;
#pragma unroll
        for (int k = 0; k < 32; k += 4) {
            fma2(a0, w[k],     hv[k]);
            fma2(a1, w[k + 1], hv[k + 1]);
            fma2(a2, w[k + 2], hv[k + 2]);
            fma2(a3, w[k + 3], hv[k + 3]);
        }
        S[tid] = unpack_sum(a0) + unpack_sum(a1) + unpack_sum(a2) + unpack_sum(a3) + bias;
        __syncthreads();

        // combine L0 (produces h0[t])
        if (t < 512 && tid < 64) {
            float r = sigm(gi0s[tid] + S[tid]);
            float z = sigm(gi0s[64 + tid] + S[64 + tid]);
            float n = tanh_f(gi0s[128 + tid] + r * S[128 + tid]);
            h0s[tid] = (1.f - z) * n + z * h0s[tid];
        }
        // combine L1 (produces h1[t-1])
        if (t >= 1 && tid >= 64 && tid < 128) {
            int j = tid - 64;
            float r = sigm(S[192 + j] + S[384 + j]);
            float z = sigm(S[256 + j] + S[448 + j]);
            float n = tanh_f(S[320 + j] + r * S[512 + j]);
            h1s[j] = (1.f - z) * n + z * h1s[j];
        }
        __syncthreads();
        gi_cur = gi_next;
    }

    // head: out[graph] = Wl @ h1 + bl
    if (tid < OUTD) {
        float acc = bl[tid];
        const float* wr = Wl + tid * 64;
#pragma unroll 8
        for (int k = 0; k < 64; k++) acc = fmaf(h1s[k], wr[k], acc);
        out[graph * OUTD + tid] = acc;
    }
}

// ---------------- launch ----------------
extern "C" void kernel_launch(void* const* d_in, const int* in_sizes, int n_in,
                              void* d_out, int out_size) {
    const float* x      = (const float*)d_in[0];
    const int*   ei     = (const int*)d_in[1];
    const float* W1     = (const float*)d_in[3];
    const float* a_src1 = (const float*)d_in[4];
    const float* a_dst1 = (const float*)d_in[5];
    const float* b1     = (const float*)d_in[6];
    const float* W2     = (const float*)d_in[7];
    const float* a_src2 = (const float*)d_in[8];
    const float* a_dst2 = (const float*)d_in[9];
    const float* b2     = (const float*)d_in[10];
    const float* Wih0   = (const float*)d_in[11];
    const float* Whh0   = (const float*)d_in[12];
    const float* bih0   = (const float*)d_in[13];
    const float* bhh0   = (const float*)d_in[14];
    const float* Wih1   = (const float*)d_in[15];
    const float* Whh1   = (const float*)d_in[16];
    const float* bih1   = (const float*)d_in[17];
    const float* bhh1   = (const float*)d_in[18];
    const float* Wl     = (const float*)d_in[19];
    const float* bl     = (const float*)d_in[20];
    float* out = (float*)d_out;

    cudaFuncSetAttribute(gat2_gemm_kernel,
                         cudaFuncAttributeMaxDynamicSharedMemorySize, 82432);
    cudaFuncSetAttribute(gru_in_gemm_kernel,
                         cudaFuncAttributeMaxDynamicSharedMemorySize, 51200);

    zero_deg_kernel<<<128, 256>>>();
    hist_kernel<<<2176, 256>>>(ei);
    scan_kernel<<<1, 1024>>>();
    scatter_kernel<<<2176, 256>>>(ei);

    gat1_gemm_kernel<<<2048, 256>>>(x, W1, a_src1, a_dst1);
    gat1_agg_kernel<<<4096, 256>>>(b1);

    gat2_gemm_kernel<<<512, 256, 82432>>>(W2, a_src2, a_dst2);
    gat2_agg_kernel<<<4096, 256>>>(b2);

    transpose_wih_kernel<<<48, 256>>>(Wih0);
    gru_in_gemm_kernel<<<512, 192, 51200>>>(bih0);

    gru_fused_kernel<<<64, 576>>>(Whh0, bhh0, Wih1, bih1, Whh1, bhh1, Wl, bl, out);
}

// round 4
// speedup vs baseline: 2.3600x; 1.0372x over previous
#include <cuda_runtime.h>
#include <cuda_bf16.h>

#define NN    32768
#define FIN   32
#define HC    64
#define HEADS 4
#define EE    524288
#define ET    (EE + NN)     // 557056 edges incl. self-loops
#define BATCH 64
#define TT    512
#define OUTD  24

// ---------------- scratch (device globals; no allocation) ----------------
__device__ __align__(16) float g_h1[(size_t)NN * 256];     // GAT1 GEMM out
__device__ __align__(16) float g_h2in[(size_t)NN * 256];   // GAT1 agg + b1 + elu
__device__ __align__(16) float g_t2[(size_t)NN * 64];      // GAT2 GEMM out
__device__ __align__(16) float g_seqin[(size_t)NN * 64];   // GAT2 agg + b2 + elu
__device__ __align__(16) float g_gi[(size_t)NN * 192];     // GRU L0 input gates
__device__ __align__(16) float g_as1[NN * 4];
__device__ __align__(16) float g_ad1[NN * 4];
__device__ float g_as2[NN];
__device__ float g_ad2[NN];
__device__ int   g_deg[NN];
__device__ int   g_rowptr[NN + 1];
__device__ int   g_cursor[NN];
__device__ int   g_csr[ET];

// ---------------- helpers ----------------
__device__ __forceinline__ float lrelu(float v)  { return v > 0.f ? v : 0.2f * v; }
__device__ __forceinline__ float elu1(float v)   { return v > 0.f ? v : (__expf(v) - 1.f); }
__device__ __forceinline__ float sigm(float v)   { return 1.f / (1.f + __expf(-v)); }
__device__ __forceinline__ float tanh_f(float v) { return 2.f / (1.f + __expf(-2.f * v)) - 1.f; }

__device__ __forceinline__ float wred(float v) {
#pragma unroll
    for (int o = 16; o; o >>= 1) v += __shfl_xor_sync(0xffffffffu, v, o);
    return v;
}
__device__ __forceinline__ float wmaxr(float v) {
#pragma unroll
    for (int o = 16; o; o >>= 1) v = fmaxf(v, __shfl_xor_sync(0xffffffffu, v, o));
    return v;
}

// packed fp32x2 FMA (sm_103a FFMA2)
__device__ __forceinline__ void fma2(unsigned long long& acc,
                                     unsigned long long a, unsigned long long b) {
    asm("fma.rn.f32x2 %0, %1, %2, %0;" : "+l"(acc) : "l"(a), "l"(b));
}
__device__ __forceinline__ float unpack_sum(unsigned long long v) {
    unsigned lo = (unsigned)v, hi = (unsigned)(v >> 32);
    return __uint_as_float(lo) + __uint_as_float(hi);
}

// ---------------- CSR build ----------------
__global__ void zero_deg_kernel() {
    int i = blockIdx.x * blockDim.x + threadIdx.x;
    if (i < NN) g_deg[i] = 0;
}

__global__ void hist_kernel(const int* __restrict__ ei) {
    int i = blockIdx.x * blockDim.x + threadIdx.x;
    if (i >= ET) return;
    int dst = (i < EE) ? ei[EE + i] : (i - EE);
    atomicAdd(&g_deg[dst], 1);
}

__global__ void scan_kernel() {   // 1 block, 1024 threads, 32 nodes/thread
    __shared__ int wsum[32];
    int tid = threadIdx.x;
    int vals[32];
    int base = tid * 32;
    int s = 0;
#pragma unroll
    for (int j = 0; j < 32; j++) { int v = g_deg[base + j]; vals[j] = v; s += v; }
    int lane = tid & 31, wid = tid >> 5;
    int inc = s;
#pragma unroll
    for (int o = 1; o < 32; o <<= 1) {
        int y = __shfl_up_sync(0xffffffffu, inc, o);
        if (lane >= o) inc += y;
    }
    if (lane == 31) wsum[wid] = inc;
    __syncthreads();
    if (wid == 0) {
        int v = wsum[lane];
#pragma unroll
        for (int o = 1; o < 32; o <<= 1) {
            int y = __shfl_up_sync(0xffffffffu, v, o);
            if (lane >= o) v += y;
        }
        wsum[lane] = v;
    }
    __syncthreads();
    int off = inc - s + (wid > 0 ? wsum[wid - 1] : 0);
#pragma unroll
    for (int j = 0; j < 32; j++) {
        g_rowptr[base + j] = off;
        g_cursor[base + j] = off;
        off += vals[j];
    }
    if (tid == 1023) g_rowptr[NN] = off;
}

__global__ void scatter_kernel(const int* __restrict__ ei) {
    int i = blockIdx.x * blockDim.x + threadIdx.x;
    if (i >= ET) return;
    int src, dst;
    if (i < EE) { src = ei[i]; dst = ei[EE + i]; }
    else        { src = dst = i - EE; }
    int pos = atomicAdd(&g_cursor[dst], 1);
    g_csr[pos] = src;
}

// ---------------- GAT layer 1: GEMM + attention coefficients ----------------
__device__ __forceinline__ void gat1_store_alpha(int node, const float acc[8],
                                                 const float* aS, const float* aD, int lane) {
#pragma unroll
    for (int j = 0; j < 8; j++) g_h1[(size_t)node * 256 + lane + 32 * j] = acc[j];
    float p0 = acc[0] * aS[lane]       + acc[1] * aS[lane + 32];
    float p1 = acc[2] * aS[64 + lane]  + acc[3] * aS[96 + lane];
    float p2 = acc[4] * aS[128 + lane] + acc[5] * aS[160 + lane];
    float p3 = acc[6] * aS[192 + lane] + acc[7] * aS[224 + lane];
    float q0 = acc[0] * aD[lane]       + acc[1] * aD[lane + 32];
    float q1 = acc[2] * aD[64 + lane]  + acc[3] * aD[96 + lane];
    float q2 = acc[4] * aD[128 + lane] + acc[5] * aD[160 + lane];
    float q3 = acc[6] * aD[192 + lane] + acc[7] * aD[224 + lane];
    p0 = wred(p0); p1 = wred(p1); p2 = wred(p2); p3 = wred(p3);
    q0 = wred(q0); q1 = wred(q1); q2 = wred(q2); q3 = wred(q3);
    if (lane == 0) {
        *(float4*)&g_as1[(size_t)node * 4] = make_float4(p0, p1, p2, p3);
        *(float4*)&g_ad1[(size_t)node * 4] = make_float4(q0, q1, q2, q3);
    }
}

__global__ __launch_bounds__(256) void gat1_gemm_kernel(
        const float* __restrict__ x, const float* __restrict__ W1,
        const float* __restrict__ a_src, const float* __restrict__ a_dst) {
    __shared__ float W1s[FIN * 256];   // 32 KB, k-major (same layout as W1)
    __shared__ float xs[16 * FIN];
    __shared__ float aS[256], aD[256];
    int tid = threadIdx.x, lane = tid & 31, w = tid >> 5;
#pragma unroll
    for (int i = 0; i < 8; i++)
        ((float4*)W1s)[tid + 256 * i] = ((const float4*)W1)[tid + 256 * i];
    aS[tid] = a_src[tid];
    aD[tid] = a_dst[tid];
    int nodeBase = blockIdx.x * 16 + w * 2;
    xs[(w * 2) * FIN + lane]     = x[(size_t)nodeBase * FIN + lane];
    xs[(w * 2 + 1) * FIN + lane] = x[(size_t)(nodeBase + 1) * FIN + lane];
    __syncthreads();
    float acc0[8] = {0,0,0,0,0,0,0,0};
    float acc1[8] = {0,0,0,0,0,0,0,0};
#pragma unroll 4
    for (int k = 0; k < FIN; k++) {
        float x0 = xs[(w * 2) * FIN + k];
        float x1 = xs[(w * 2 + 1) * FIN + k];
#pragma unroll
        for (int j = 0; j < 8; j++) {
            float wv = W1s[k * 256 + lane + 32 * j];
            acc0[j] = fmaf(x0, wv, acc0[j]);
            acc1[j] = fmaf(x1, wv, acc1[j]);
        }
    }
    gat1_store_alpha(nodeBase,     acc0, aS, aD, lane);
    gat1_store_alpha(nodeBase + 1, acc1, aS, aD, lane);
}

// ---------------- GAT layer 1 aggregation: 2 warps/node, fused sum+gather ----
__global__ __launch_bounds__(256) void gat1_agg_kernel(const float* __restrict__ b1) {
    int wid = threadIdx.x >> 5, lane = threadIdx.x & 31;
    int node = blockIdx.x * 4 + (wid >> 1);
    int half = wid & 1;                      // heads {0,1} or {2,3}
    int beg = g_rowptr[node], end = g_rowptr[node + 1];
    const float2* asp = (const float2*)g_as1;
    float2 ad = ((const float2*)g_ad1)[node * 2 + half];

    // pass 1: max (lane-parallel)
    float m0 = -1e30f, m1 = -1e30f;
    for (int e = beg + lane; e < end; e += 32) {
        int s = __ldg(&g_csr[e]);
        float2 as = __ldg(&asp[s * 2 + half]);
        m0 = fmaxf(m0, lrelu(as.x + ad.x));
        m1 = fmaxf(m1, lrelu(as.y + ad.y));
    }
    m0 = wmaxr(m0); m1 = wmaxr(m1);

    // pass 2 (fused): unnormalized weighted gather + sum, 2-edge unroll
    float acc0 = 0.f, acc1 = 0.f, acc2 = 0.f, acc3 = 0.f;
    float s0 = 0.f, s1 = 0.f;
    const float* base = g_h1 + half * 128 + lane;
    int e = beg;
    for (; e + 1 < end; e += 2) {
        int sa = __ldg(&g_csr[e]);
        int sb = __ldg(&g_csr[e + 1]);
        float2 aa = __ldg(&asp[sa * 2 + half]);
        float2 ab = __ldg(&asp[sb * 2 + half]);
        const float* ha = base + (size_t)sa * 256;
        const float* hb = base + (size_t)sb * 256;
        float va0 = ha[0], va1 = ha[32], va2 = ha[64], va3 = ha[96];
        float vb0 = hb[0], vb1 = hb[32], vb2 = hb[64], vb3 = hb[96];
        float wa0 = __expf(lrelu(aa.x + ad.x) - m0);
        float wa1 = __expf(lrelu(aa.y + ad.y) - m1);
        float wb0 = __expf(lrelu(ab.x + ad.x) - m0);
        float wb1 = __expf(lrelu(ab.y + ad.y) - m1);
        s0 += wa0 + wb0; s1 += wa1 + wb1;
        acc0 = fmaf(va0, wa0, fmaf(vb0, wb0, acc0));
        acc1 = fmaf(va1, wa0, fmaf(vb1, wb0, acc1));
        acc2 = fmaf(va2, wa1, fmaf(vb2, wb1, acc2));
        acc3 = fmaf(va3, wa1, fmaf(vb3, wb1, acc3));
    }
    if (e < end) {
        int sa = __ldg(&g_csr[e]);
        float2 aa = __ldg(&asp[sa * 2 + half]);
        const float* ha = base + (size_t)sa * 256;
        float wa0 = __expf(lrelu(aa.x + ad.x) - m0);
        float wa1 = __expf(lrelu(aa.y + ad.y) - m1);
        s0 += wa0; s1 += wa1;
        acc0 = fmaf(ha[0],  wa0, acc0);
        acc1 = fmaf(ha[32], wa0, acc1);
        acc2 = fmaf(ha[64], wa1, acc2);
        acc3 = fmaf(ha[96], wa1, acc3);
    }
    float i0 = 1.f / (s0 + 1e-16f), i1 = 1.f / (s1 + 1e-16f);
    int c = half * 128 + lane;
    float* dst = g_h2in + (size_t)node * 256;
    dst[c]      = elu1(acc0 * i0 + __ldg(&b1[c]));
    dst[c + 32] = elu1(acc1 * i0 + __ldg(&b1[c + 32]));
    dst[c + 64] = elu1(acc2 * i1 + __ldg(&b1[c + 64]));
    dst[c + 96] = elu1(acc3 * i1 + __ldg(&b1[c + 96]));
}

// ---------------- GAT layer 2: register-tiled GEMM (128n x 64c, k-chunk 64) --
// dyn smem: A[64][132] + W[64][64]  = 50176 B
__global__ __launch_bounds__(256) void gat2_gemm_kernel(const float* __restrict__ W2) {
    extern __shared__ float sm[];
    float* As = sm;                 // 64 x 132
    float* Ws = sm + 64 * 132;      // 64 x 64
    int tid = threadIdx.x;
    int tx = tid & 15, cy = tid >> 4;
    int n0 = blockIdx.x * 128;
    float acc[8][4];
#pragma unroll
    for (int i = 0; i < 8; i++)
#pragma unroll
        for (int j = 0; j < 4; j++) acc[i][j] = 0.f;

    for (int k0 = 0; k0 < 256; k0 += 64) {
        // load A transposed: g_h2in[n0+node][k0+k] -> As[k][node]
#pragma unroll
        for (int i = 0; i < 8; i++) {
            int f = tid + 256 * i;              // 0..2047
            int node = f >> 4, kq = f & 15;
            float4 v = *(const float4*)&g_h2in[(size_t)(n0 + node) * 256 + k0 + kq * 4];
            As[(kq * 4 + 0) * 132 + node] = v.x;
            As[(kq * 4 + 1) * 132 + node] = v.y;
            As[(kq * 4 + 2) * 132 + node] = v.z;
            As[(kq * 4 + 3) * 132 + node] = v.w;
        }
        // load W: W2[k0+k][c] -> Ws[k][c] (already k-major)
#pragma unroll
        for (int i = 0; i < 4; i++) {
            int f = tid + 256 * i;              // 0..1023
            int k = f >> 4, cq = f & 15;
            *(float4*)&Ws[k * 64 + cq * 4] = *(const float4*)&W2[(size_t)(k0 + k) * 64 + cq * 4];
        }
        __syncthreads();
#pragma unroll 16
        for (int k = 0; k < 64; k++) {
            float4 a0 = *(float4*)&As[k * 132 + tx * 8];
            float4 a1 = *(float4*)&As[k * 132 + tx * 8 + 4];
            float4 wv = *(float4*)&Ws[k * 64 + cy * 4];
            float av[8] = {a0.x, a0.y, a0.z, a0.w, a1.x, a1.y, a1.z, a1.w};
#pragma unroll
            for (int i = 0; i < 8; i++) {
                acc[i][0] = fmaf(av[i], wv.x, acc[i][0]);
                acc[i][1] = fmaf(av[i], wv.y, acc[i][1]);
                acc[i][2] = fmaf(av[i], wv.z, acc[i][2]);
                acc[i][3] = fmaf(av[i], wv.w, acc[i][3]);
            }
        }
        __syncthreads();
    }
#pragma unroll
    for (int i = 0; i < 8; i++) {
        int node = n0 + tx * 8 + i;
        *(float4*)&g_t2[(size_t)node * 64 + cy * 4] =
            make_float4(acc[i][0], acc[i][1], acc[i][2], acc[i][3]);
    }
}

// ---------------- alpha coefficients for layer 2 (warp per node) -------------
__global__ __launch_bounds__(256) void alpha2_kernel(const float* __restrict__ a_src,
                                                     const float* __restrict__ a_dst) {
    int node = blockIdx.x * 8 + (threadIdx.x >> 5);
    int lane = threadIdx.x & 31;
    float t0 = g_t2[(size_t)node * 64 + lane];
    float t1 = g_t2[(size_t)node * 64 + lane + 32];
    float p = wred(t0 * __ldg(&a_src[lane]) + t1 * __ldg(&a_src[lane + 32]));
    float q = wred(t0 * __ldg(&a_dst[lane]) + t1 * __ldg(&a_dst[lane + 32]));
    if (lane == 0) { g_as2[node] = p; g_ad2[node] = q; }
}

// ---------------- GAT layer 2 aggregation (fused sum+gather, 2-edge unroll) --
__global__ __launch_bounds__(256) void gat2_agg_kernel(const float* __restrict__ b2) {
    int node = blockIdx.x * 8 + (threadIdx.x >> 5);
    int lane = threadIdx.x & 31;
    int beg = g_rowptr[node], end = g_rowptr[node + 1];
    float ad = g_ad2[node];
    float m = -1e30f;
    for (int e = beg + lane; e < end; e += 32)
        m = fmaxf(m, lrelu(__ldg(&g_as2[__ldg(&g_csr[e])]) + ad));
    m = wmaxr(m);
    float acc0 = 0.f, acc1 = 0.f, su = 0.f;
    const float* base = g_t2 + lane;
    int e = beg;
    for (; e + 1 < end; e += 2) {
        int sa = __ldg(&g_csr[e]);
        int sb = __ldg(&g_csr[e + 1]);
        float aa = __ldg(&g_as2[sa]);
        float ab = __ldg(&g_as2[sb]);
        const float* ta = base + (size_t)sa * 64;
        const float* tb = base + (size_t)sb * 64;
        float va0 = ta[0], va1 = ta[32], vb0 = tb[0], vb1 = tb[32];
        float wa = __expf(lrelu(aa + ad) - m);
        float wb = __expf(lrelu(ab + ad) - m);
        su += wa + wb;
        acc0 = fmaf(va0, wa, fmaf(vb0, wb, acc0));
        acc1 = fmaf(va1, wa, fmaf(vb1, wb, acc1));
    }
    if (e < end) {
        int sa = __ldg(&g_csr[e]);
        float wa = __expf(lrelu(__ldg(&g_as2[sa]) + ad) - m);
        const float* ta = base + (size_t)sa * 64;
        su += wa;
        acc0 = fmaf(ta[0],  wa, acc0);
        acc1 = fmaf(ta[32], wa, acc1);
    }
    float inv = 1.f / (su + 1e-16f);
    g_seqin[(size_t)node * 64 + lane]      = elu1(acc0 * inv + __ldg(&b2[lane]));
    g_seqin[(size_t)node * 64 + lane + 32] = elu1(acc1 * inv + __ldg(&b2[lane + 32]));
}

// ---------------- GRU L0 input GEMM: register-tiled (128n x 64j per block) ---
// grid (256, 3); dyn smem: A[64][132] + W[64][64] = 50176 B
__global__ __launch_bounds__(256) void gru_in_gemm_kernel(const float* __restrict__ Wih,
                                                          const float* __restrict__ bih) {
    extern __shared__ float sm[];
    float* As = sm;
    float* Ws = sm + 64 * 132;
    int tid = threadIdx.x;
    int tx = tid & 15, cy = tid >> 4;
    int n0 = blockIdx.x * 128;
    int j0 = blockIdx.y * 64;

    // A transposed: g_seqin[n0+node][k] -> As[k][node]
#pragma unroll
    for (int i = 0; i < 8; i++) {
        int f = tid + 256 * i;
        int node = f >> 4, kq = f & 15;
        float4 v = *(const float4*)&g_seqin[(size_t)(n0 + node) * 64 + kq * 4];
        As[(kq * 4 + 0) * 132 + node] = v.x;
        As[(kq * 4 + 1) * 132 + node] = v.y;
        As[(kq * 4 + 2) * 132 + node] = v.z;
        As[(kq * 4 + 3) * 132 + node] = v.w;
    }
    // W transposed: Wih[j0+j][k] -> Ws[k][j]
#pragma unroll
    for (int i = 0; i < 4; i++) {
        int f = tid + 256 * i;
        int j = f >> 4, kq = f & 15;
        float4 v = *(const float4*)&Wih[(size_t)(j0 + j) * 64 + kq * 4];
        Ws[(kq * 4 + 0) * 64 + j] = v.x;
        Ws[(kq * 4 + 1) * 64 + j] = v.y;
        Ws[(kq * 4 + 2) * 64 + j] = v.z;
        Ws[(kq * 4 + 3) * 64 + j] = v.w;
    }
    __syncthreads();

    float acc[8][4];
#pragma unroll
    for (int i = 0; i < 8; i++)
#pragma unroll
        for (int j = 0; j < 4; j++) acc[i][j] = 0.f;
#pragma unroll 16
    for (int k = 0; k < 64; k++) {
        float4 a0 = *(float4*)&As[k * 132 + tx * 8];
        float4 a1 = *(float4*)&As[k * 132 + tx * 8 + 4];
        float4 wv = *(float4*)&Ws[k * 64 + cy * 4];
        float av[8] = {a0.x, a0.y, a0.z, a0.w, a1.x, a1.y, a1.z, a1.w};
#pragma unroll
        for (int i = 0; i < 8; i++) {
            acc[i][0] = fmaf(av[i], wv.x, acc[i][0]);
            acc[i][1] = fmaf(av[i], wv.y, acc[i][1]);
            acc[i][2] = fmaf(av[i], wv.z, acc[i][2]);
            acc[i][3] = fmaf(av[i], wv.w, acc[i][3]);
        }
    }
    float4 bv = *(const float4*)&bih[j0 + cy * 4];
#pragma unroll
    for (int i = 0; i < 8; i++) {
        int node = n0 + tx * 8 + i;
        *(float4*)&g_gi[(size_t)node * 192 + j0 + cy * 4] =
            make_float4(acc[i][0] + bv.x, acc[i][1] + bv.y,
                        acc[i][2] + bv.z, acc[i][3] + bv.w);
    }
}

// ---------------- Fused 2-layer GRU recurrence + head ----------------
__global__ __launch_bounds__(576, 1) void gru_fused_kernel(
        const float* __restrict__ Whh0, const float* __restrict__ bhh0,
        const float* __restrict__ Wih1, const float* __restrict__ bih1,
        const float* __restrict__ Whh1, const float* __restrict__ bhh1,
        const float* __restrict__ Wl,   const float* __restrict__ bl,
        float* __restrict__ out) {
    __shared__ __align__(16) float S[576];     // [gh0 | gi1 | gh1]
    __shared__ __align__(16) float gi0s[192];
    __shared__ __align__(16) float h0s[64];
    __shared__ __align__(16) float h1s[64];

    int tid = threadIdx.x;
    int graph = blockIdx.x;

    const float* wrow;
    const float* hsrc;
    float bias;
    if (tid < 192)      { wrow = Whh0 + tid * 64;         hsrc = h0s; bias = bhh0[tid]; }
    else if (tid < 384) { wrow = Wih1 + (tid - 192) * 64; hsrc = h0s; bias = bih1[tid - 192]; }
    else                { wrow = Whh1 + (tid - 384) * 64; hsrc = h1s; bias = bhh1[tid - 384]; }

    unsigned long long w[32];
    const unsigned long long* wp = (const unsigned long long*)wrow;
#pragma unroll
    for (int i = 0; i < 32; i++) w[i] = wp[i];

    if (tid < 64) { h0s[tid] = 0.f; h1s[tid] = 0.f; }

    const float* gi = g_gi + (size_t)graph * 512 * 192;
    float gi_cur = 0.f;
    if (tid < 192) gi_cur = gi[tid];
    __syncthreads();

    const unsigned long long* hv = (const unsigned long long*)hsrc;

    for (int t = 0; t <= 512; t++) {
        float gi_next = 0.f;
        if (tid < 192) {
            gi0s[tid] = gi_cur;
            int tn = (t + 1 < 512) ? (t + 1) : 511;
            gi_next = gi[(size_t)tn * 192 + tid];
        }
        unsigned long long a0 = 0, a1 = 0, a2 = 0, a3 = 0;
#pragma unroll
        for (int k = 0; k < 32; k += 4) {
            fma2(a0, w[k],     hv[k]);
            fma2(a1, w[k + 1], hv[k + 1]);
            fma2(a2, w[k + 2], hv[k + 2]);
            fma2(a3, w[k + 3], hv[k + 3]);
        }
        S[tid] = unpack_sum(a0) + unpack_sum(a1) + unpack_sum(a2) + unpack_sum(a3) + bias;
        __syncthreads();

        if (t < 512 && tid < 64) {
            float r = sigm(gi0s[tid] + S[tid]);
            float z = sigm(gi0s[64 + tid] + S[64 + tid]);
            float n = tanh_f(gi0s[128 + tid] + r * S[128 + tid]);
            h0s[tid] = (1.f - z) * n + z * h0s[tid];
        }
        if (t >= 1 && tid >= 64 && tid < 128) {
            int j = tid - 64;
            float r = sigm(S[192 + j] + S[384 + j]);
            float z = sigm(S[256 + j] + S[448 + j]);
            float n = tanh_f(S[320 + j] + r * S[512 + j]);
            h1s[j] = (1.f - z) * n + z * h1s[j];
        }
        __syncthreads();
        gi_cur = gi_next;
    }

    if (tid < OUTD) {
        float acc = bl[tid];
        const float* wr = Wl + tid * 64;
#pragma unroll 8
        for (int k = 0; k < 64; k++) acc = fmaf(h1s[k], wr[k], acc);
        out[graph * OUTD + tid] = acc;
    }
}

// ---------------- launch ----------------
extern "C" void kernel_launch(void* const* d_in, const int* in_sizes, int n_in,
                              void* d_out, int out_size) {
    const float* x      = (const float*)d_in[0];
    const int*   ei     = (const int*)d_in[1];
    const float* W1     = (const float*)d_in[3];
    const float* a_src1 = (const float*)d_in[4];
    const float* a_dst1 = (const float*)d_in[5];
    const float* b1     = (const float*)d_in[6];
    const float* W2     = (const float*)d_in[7];
    const float* a_src2 = (const float*)d_in[8];
    const float* a_dst2 = (const float*)d_in[9];
    const float* b2     = (const float*)d_in[10];
    const float* Wih0   = (const float*)d_in[11];
    const float* Whh0   = (const float*)d_in[12];
    const float* bih0   = (const float*)d_in[13];
    const float* bhh0   = (const float*)d_in[14];
    const float* Wih1   = (const float*)d_in[15];
    const float* Whh1   = (const float*)d_in[16];
    const float* bih1   = (const float*)d_in[17];
    const float* bhh1   = (const float*)d_in[18];
    const float* Wl     = (const float*)d_in[19];
    const float* bl     = (const float*)d_in[20];
    float* out = (float*)d_out;

    cudaFuncSetAttribute(gat2_gemm_kernel,
                         cudaFuncAttributeMaxDynamicSharedMemorySize, 50176);
    cudaFuncSetAttribute(gru_in_gemm_kernel,
                         cudaFuncAttributeMaxDynamicSharedMemorySize, 50176);

    zero_deg_kernel<<<128, 256>>>();
    hist_kernel<<<2176, 256>>>(ei);
    scan_kernel<<<1, 1024>>>();
    scatter_kernel<<<2176, 256>>>(ei);

    gat1_gemm_kernel<<<2048, 256>>>(x, W1, a_src1, a_dst1);
    gat1_agg_kernel<<<8192, 256>>>(b1);

    gat2_gemm_kernel<<<256, 256, 50176>>>(W2);
    alpha2_kernel<<<4096, 256>>>(a_src2, a_dst2);
    gat2_agg_kernel<<<4096, 256>>>(b2);

    gru_in_gemm_kernel<<<dim3(256, 3), 256, 50176>>>(Wih0, bih0);

    gru_fused_kernel<<<64, 576>>>(Whh0, bhh0, Wih1, bih1, Whh1, bhh1, Wl, bl, out);
}